// round 7
// baseline (speedup 1.0000x reference)
#include <cuda_runtime.h>
#include <cuda_bf16.h>
#include <cstdint>

#define N_B 4096
#define NROWS (N_B * 256)
#define NTHREADS 384
#define TILE_ROWS 192

// ---------------- smem layout (bytes) ----------------
#define SM_BH    0        // 32768  W2_hi  [n][k] bf16, swizzled
#define SM_BL    32768    // 32768  W2_lo
#define SM_AH    65536    // 49152  A_hi   [m=192][k] bf16, swizzled
#define SM_AL    114688   // 49152  A_lo
#define SM_W1    163840   // 4096   W1 [k][col] f32
#define SM_EPI   167936   // 2048   per-col float4 {b2, w3_0, w3_1, 0}
#define SM_B1    169984   // 512
#define SM_FEAT  170496   // 6144   feat[192][8] f32
#define SM_B3    176640   // 8
#define SMEM_TOTAL 176648

// ---------------- helpers ----------------
__device__ __forceinline__ uint32_t smem_u32_of(const void* p) {
    uint32_t a;
    asm("{ .reg .u64 t; cvta.to.shared.u64 t, %1; cvt.u32.u64 %0, t; }" : "=r"(a) : "l"(p));
    return a;
}
__device__ __forceinline__ unsigned long long pack_dup(float v) {
    unsigned long long r; asm("mov.b64 %0, {%1, %1};" : "=l"(r) : "f"(v)); return r;
}
__device__ __forceinline__ unsigned long long ffma2(unsigned long long a, unsigned long long b,
                                                    unsigned long long c) {
    unsigned long long d; asm("fma.rn.f32x2 %0, %1, %2, %3;" : "=l"(d) : "l"(a), "l"(b), "l"(c));
    return d;
}
__device__ __forceinline__ float2 unpack2(unsigned long long v) {
    float2 r; asm("mov.b64 {%0, %1}, %2;" : "=f"(r.x), "=f"(r.y) : "l"(v)); return r;
}
__device__ __forceinline__ uint32_t cvt2bf(float hi, float lo) {  // hi->upper16, lo->lower16
    uint32_t r; asm("cvt.rn.bf16x2.f32 %0, %1, %2;" : "=r"(r) : "f"(hi), "f"(lo)); return r;
}
__device__ __forceinline__ void ldsm4(uint32_t* r, uint32_t addr) {
    asm volatile("ldmatrix.sync.aligned.m8n8.x4.shared.b16 {%0,%1,%2,%3}, [%4];"
                 : "=r"(r[0]), "=r"(r[1]), "=r"(r[2]), "=r"(r[3]) : "r"(addr));
}
__device__ __forceinline__ void mma16816(float* d, const uint32_t* a, uint32_t b0, uint32_t b1) {
    asm volatile("mma.sync.aligned.m16n8k16.row.col.f32.bf16.bf16.f32 "
                 "{%0,%1,%2,%3}, {%4,%5,%6,%7}, {%8,%9}, {%0,%1,%2,%3};"
                 : "+f"(d[0]), "+f"(d[1]), "+f"(d[2]), "+f"(d[3])
                 : "r"(a[0]), "r"(a[1]), "r"(a[2]), "r"(a[3]), "r"(b0), "r"(b1));
}

// per-warp conv: features + L1 + bf16 hi/lo split for this warp's 16 rows.
template <int DIR>
__device__ __forceinline__ void conv_warp(char* sm, const float* __restrict__ x,
                                          const float* __restrict__ t, long grow0,
                                          int wid, int lane)
{
    const int r0 = wid * 16;
    float* sFeat = (float*)(sm + SM_FEAT);
    if (lane < 16) {
        const int m = r0 + lane;
        long g = grow0 + m;
        if (g >= NROWS) g = NROWS - 1;          // clamp: garbage rows masked at store
        const int b = (int)(g >> 8), i = (int)(g & 255);
        const float* xb = x + (size_t)b * 514;
        const float2 xi  = *(const float2*)(xb + i * 2);
        const float2 xi1 = *(const float2*)(xb + i * 2 + 2);
        const float2 pt  = *(const float2*)(xb + 512);
        const float tb = t[b];
        float* f = sFeat + m * 8;
        if (DIR == 0) { f[0]=xi1.x; f[1]=xi1.y; f[2]=tb; f[3]=xi.x;  f[4]=xi.y;  f[5]=(float)(i+1)*(1.f/256.f); }
        else          { f[0]=xi.x;  f[1]=xi.y;  f[2]=tb; f[3]=xi1.x; f[4]=xi1.y; f[5]=(float)i*(1.f/256.f); }
        f[6]=pt.x; f[7]=pt.y;
    }
    __syncwarp();

    const float* sW1 = (const float*)(sm + SM_W1);
    unsigned long long w1p[16];
    #pragma unroll
    for (int k = 0; k < 8; k++) {
        const ulonglong2 q = *(const ulonglong2*)(sW1 + k * 128 + lane * 4);
        w1p[2 * k] = q.x; w1p[2 * k + 1] = q.y;
    }
    const ulonglong2 b1q = *(const ulonglong2*)((const float*)(sm + SM_B1) + lane * 4);

    char* ah = sm + SM_AH;
    char* al = sm + SM_AL;
    const uint32_t chk = lane >> 1;
    const uint32_t halfsel = (lane & 1) * 8;
    #pragma unroll 4
    for (int j = 0; j < 16; j++) {
        const int m = r0 + j;
        const float* f = sFeat + m * 8;
        const float4 fa = *(const float4*)(f);
        const float4 fb = *(const float4*)(f + 4);
        unsigned long long a0 = b1q.x, a1 = b1q.y;
        a0 = ffma2(pack_dup(fa.x), w1p[0],  a0); a1 = ffma2(pack_dup(fa.x), w1p[1],  a1);
        a0 = ffma2(pack_dup(fa.y), w1p[2],  a0); a1 = ffma2(pack_dup(fa.y), w1p[3],  a1);
        a0 = ffma2(pack_dup(fa.z), w1p[4],  a0); a1 = ffma2(pack_dup(fa.z), w1p[5],  a1);
        a0 = ffma2(pack_dup(fa.w), w1p[6],  a0); a1 = ffma2(pack_dup(fa.w), w1p[7],  a1);
        a0 = ffma2(pack_dup(fb.x), w1p[8],  a0); a1 = ffma2(pack_dup(fb.x), w1p[9],  a1);
        a0 = ffma2(pack_dup(fb.y), w1p[10], a0); a1 = ffma2(pack_dup(fb.y), w1p[11], a1);
        a0 = ffma2(pack_dup(fb.z), w1p[12], a0); a1 = ffma2(pack_dup(fb.z), w1p[13], a1);
        a0 = ffma2(pack_dup(fb.w), w1p[14], a0); a1 = ffma2(pack_dup(fb.w), w1p[15], a1);
        const float2 v01 = unpack2(a0), v23 = unpack2(a1);
        const float v0 = fmaxf(v01.x, 0.f), v1 = fmaxf(v01.y, 0.f);
        const float v2 = fmaxf(v23.x, 0.f), v3 = fmaxf(v23.y, 0.f);
        const uint32_t h0 = cvt2bf(v1, v0), h1 = cvt2bf(v3, v2);
        const float g0 = __uint_as_float(h0 << 16), g1 = __uint_as_float(h0 & 0xffff0000u);
        const float g2 = __uint_as_float(h1 << 16), g3 = __uint_as_float(h1 & 0xffff0000u);
        const uint32_t l0 = cvt2bf(v1 - g1, v0 - g0), l1 = cvt2bf(v3 - g3, v2 - g2);
        const uint32_t off = (uint32_t)m * 256 + (((chk ^ (uint32_t)(m & 7)) << 4)) + halfsel;
        *(uint2*)(ah + off) = make_uint2(h0, h1);
        *(uint2*)(al + off) = make_uint2(l0, l1);
    }
    __syncwarp();
}

// guarded output for one row
template <int DIR>
__device__ __forceinline__ void store_row(float* __restrict__ out, long g, float p0, float p1) {
    if (g >= NROWS) return;
    const int b = (int)(g >> 8), i = (int)(g & 255);
    float* ob = out + (size_t)b * 512;
    if (DIR == 0) {
        if (i == 0) *(float2*)ob = make_float2(0.f, 0.f);
        if (i < 255) *(float2*)(ob + (i + 1) * 2) = make_float2(p0, p1);
    } else {
        if (i < 255) {
            float2* o = (float2*)(ob + i * 2);
            const float2 v = *o; *o = make_float2(v.x + p0, v.y + p1);
        }
    }
}

template <int DIR>
__global__ void __launch_bounds__(NTHREADS, 1)
fused_kernel(const float* __restrict__ x, const float* __restrict__ t,
             const float* __restrict__ W1, const float* __restrict__ b1v,
             const float* __restrict__ W2, const float* __restrict__ b2v,
             const float* __restrict__ W3, const float* __restrict__ b3v,
             float* __restrict__ out, int ntiles)
{
    extern __shared__ __align__(1024) char sm[];
    const int tid = threadIdx.x, wid = tid >> 5, lane = tid & 31;
    const uint32_t smb = smem_u32_of(sm);

    // ---- prologue: split + transpose W2 into [n][k] hi/lo, small weights ----
    for (int idx = tid; idx < 16384; idx += NTHREADS) {
        const int n = idx >> 7, k = idx & 127;
        const float w = W2[k * 128 + n];
        const __nv_bfloat16 hb = __float2bfloat16(w);
        const __nv_bfloat16 lb = __float2bfloat16(w - __bfloat162float(hb));
        const uint32_t off = (uint32_t)n * 256 + ((((uint32_t)(k >> 3) ^ (uint32_t)(n & 7)) << 4)) +
                             (uint32_t)(k & 7) * 2;
        *(__nv_bfloat16*)(sm + SM_BH + off) = hb;
        *(__nv_bfloat16*)(sm + SM_BL + off) = lb;
    }
    float* sW1 = (float*)(sm + SM_W1);
    for (int idx = tid; idx < 1024; idx += NTHREADS) sW1[idx] = W1[idx];
    if (tid < 128) {
        float4 e; e.x = b2v[tid]; e.y = W3[tid * 2]; e.z = W3[tid * 2 + 1]; e.w = 0.f;
        ((float4*)(sm + SM_EPI))[tid] = e;
        ((float*)(sm + SM_B1))[tid] = b1v[tid];
    }
    if (tid == 0) ((float2*)(sm + SM_B3))[0] = make_float2(b3v[0], b3v[1]);
    __syncthreads();

    const float2 b3 = ((const float2*)(sm + SM_B3))[0];

    // ldmatrix lane-address components
    const uint32_t rA = (uint32_t)(wid * 16) + (uint32_t)(lane & 15);
    const uint32_t rowA_off = rA * 256;
    const uint32_t rxA = rA & 7;
    const uint32_t cA_bit = (uint32_t)(lane >> 4);
    const uint32_t nB = (uint32_t)(lane & 7) + (uint32_t)((lane & 16) >> 1);
    const uint32_t rowB_off = nB * 256;
    const uint32_t rxB = nB & 7;
    const uint32_t cB_bit = (uint32_t)((lane >> 3) & 1);

    const uint32_t aH = smb + SM_AH, aL = smb + SM_AL;
    const uint32_t bH = smb + SM_BH, bL = smb + SM_BL;
    const float4* epi = (const float4*)(sm + SM_EPI);

    for (int tt = blockIdx.x; tt < ntiles; tt += gridDim.x) {
        const long grow0 = (long)tt * TILE_ROWS;
        conv_warp<DIR>(sm, x, t, grow0, wid, lane);

        float acc[16][4];
        #pragma unroll
        for (int nb = 0; nb < 16; nb++)
            { acc[nb][0] = 0.f; acc[nb][1] = 0.f; acc[nb][2] = 0.f; acc[nb][3] = 0.f; }

        #pragma unroll
        for (int kb = 0; kb < 8; kb++) {
            const uint32_t cA = (uint32_t)(2 * kb) + cA_bit;
            const uint32_t offA = rowA_off + ((cA ^ rxA) << 4);
            uint32_t ah[4], al[4];
            ldsm4(ah, aH + offA);
            ldsm4(al, aL + offA);
            const uint32_t cB = (uint32_t)(2 * kb) + cB_bit;
            const uint32_t offB0 = rowB_off + ((cB ^ rxB) << 4);
            #pragma unroll
            for (int nb2 = 0; nb2 < 8; nb2++) {
                uint32_t bh[4], bl[4];
                const uint32_t offB = offB0 + (uint32_t)nb2 * 4096;
                ldsm4(bh, bH + offB);
                ldsm4(bl, bL + offB);
                mma16816(acc[2 * nb2],     ah, bh[0], bh[1]);
                mma16816(acc[2 * nb2],     ah, bl[0], bl[1]);
                mma16816(acc[2 * nb2],     al, bh[0], bh[1]);
                mma16816(acc[2 * nb2 + 1], ah, bh[2], bh[3]);
                mma16816(acc[2 * nb2 + 1], ah, bl[2], bl[3]);
                mma16816(acc[2 * nb2 + 1], al, bh[2], bh[3]);
            }
        }

        // ---- epilogue: relu(acc + b2) @ W3, 4-lane reduce, guarded store ----
        float pa0 = 0.f, pa1 = 0.f, pb0 = 0.f, pb1 = 0.f;
        #pragma unroll
        for (int nb = 0; nb < 16; nb++) {
            const int col0 = nb * 8 + 2 * (lane & 3);
            const float4 e0 = epi[col0], e1 = epi[col0 + 1];
            float v;
            v = fmaxf(acc[nb][0] + e0.x, 0.f); pa0 += v * e0.y; pa1 += v * e0.z;
            v = fmaxf(acc[nb][1] + e1.x, 0.f); pa0 += v * e1.y; pa1 += v * e1.z;
            v = fmaxf(acc[nb][2] + e0.x, 0.f); pb0 += v * e0.y; pb1 += v * e0.z;
            v = fmaxf(acc[nb][3] + e1.x, 0.f); pb0 += v * e1.y; pb1 += v * e1.z;
        }
        #pragma unroll
        for (int s = 1; s <= 2; s <<= 1) {
            pa0 += __shfl_xor_sync(0xffffffffu, pa0, s);
            pa1 += __shfl_xor_sync(0xffffffffu, pa1, s);
            pb0 += __shfl_xor_sync(0xffffffffu, pb0, s);
            pb1 += __shfl_xor_sync(0xffffffffu, pb1, s);
        }
        if ((lane & 3) == 0) {
            const int q = lane >> 2;
            const long g1 = grow0 + wid * 16 + q;    // rows g1 and g1+8
            store_row<DIR>(out, g1,     pa0 + b3.x, pa1 + b3.y);
            store_row<DIR>(out, g1 + 8, pb0 + b3.x, pb1 + b3.y);
        }
        __syncwarp();
    }
}

// ---------------- init MLP (3->128->128->2, 4096 rows) ----------------
__global__ void __launch_bounds__(128)
init_kernel(const float* __restrict__ x, const float* __restrict__ t,
            const float* __restrict__ W1, const float* __restrict__ b1,
            const float* __restrict__ W2, const float* __restrict__ b2,
            const float* __restrict__ W3, const float* __restrict__ b3,
            float* __restrict__ out, int nrows)
{
    extern __shared__ float ism[];
    float* sW2 = ism;           // 16384
    float* sh  = ism + 16384;   // 128
    float* red = ism + 16512;   // 8
    const int tid = threadIdx.x;
    for (int i = tid; i < 16384; i += 128) sW2[i] = W2[i];
    const float w10 = W1[tid], w11 = W1[128 + tid], w12 = W1[256 + tid];
    const float bb1 = b1[tid], bb2 = b2[tid];
    const float w30 = W3[tid * 2], w31 = W3[tid * 2 + 1];
    __syncthreads();
    for (int r = blockIdx.x; r < nrows; r += gridDim.x) {
        const float2 x0 = *(const float2*)(x + (size_t)r * 514);
        const float tb = t[r];
        sh[tid] = fmaxf(bb1 + x0.x * w10 + x0.y * w11 + tb * w12, 0.f);
        __syncthreads();
        float a = bb2;
        #pragma unroll 8
        for (int k = 0; k < 128; k++) a += sh[k] * sW2[k * 128 + tid];
        a = fmaxf(a, 0.f);
        float p0 = a * w30, p1 = a * w31;
        #pragma unroll
        for (int s = 16; s; s >>= 1) {
            p0 += __shfl_xor_sync(0xffffffffu, p0, s);
            p1 += __shfl_xor_sync(0xffffffffu, p1, s);
        }
        if ((tid & 31) == 0) { red[tid >> 5] = p0; red[4 + (tid >> 5)] = p1; }
        __syncthreads();
        if (tid == 0) {
            const float q0 = red[0] + red[1] + red[2] + red[3] + b3[0];
            const float q1 = red[4] + red[5] + red[6] + red[7] + b3[1];
            float2* o = (float2*)(out + (size_t)r * 512);
            const float2 v = *o; *o = make_float2(v.x + q0, v.y + q1);
        }
        __syncthreads();
    }
}

extern "C" void kernel_launch(void* const* d_in, const int* in_sizes, int n_in,
                              void* d_out, int out_size)
{
    (void)in_sizes; (void)n_in; (void)out_size;
    const float* x = (const float*)d_in[0];
    const float* t = (const float*)d_in[1];
    float* out = (float*)d_out;

    cudaFuncSetAttribute(fused_kernel<0>, cudaFuncAttributeMaxDynamicSharedMemorySize, SMEM_TOTAL);
    cudaFuncSetAttribute(fused_kernel<1>, cudaFuncAttributeMaxDynamicSharedMemorySize, SMEM_TOTAL);
    cudaFuncSetAttribute(init_kernel, cudaFuncAttributeMaxDynamicSharedMemorySize, 16520 * 4);

    const int ntiles = (NROWS + TILE_ROWS - 1) / TILE_ROWS;   // 5462, last tile guarded
    const int grid = 148;

    fused_kernel<0><<<grid, NTHREADS, SMEM_TOTAL>>>(x, t,
        (const float*)d_in[2], (const float*)d_in[3], (const float*)d_in[4],
        (const float*)d_in[5], (const float*)d_in[6], (const float*)d_in[7], out, ntiles);
    fused_kernel<1><<<grid, NTHREADS, SMEM_TOTAL>>>(x, t,
        (const float*)d_in[8], (const float*)d_in[9], (const float*)d_in[10],
        (const float*)d_in[11], (const float*)d_in[12], (const float*)d_in[13], out, ntiles);
    init_kernel<<<128, 128, 16520 * 4>>>(x, t,
        (const float*)d_in[14], (const float*)d_in[15], (const float*)d_in[16],
        (const float*)d_in[17], (const float*)d_in[18], (const float*)d_in[19], out, N_B);
}

// round 8
// speedup vs baseline: 1.0576x; 1.0576x over previous
#include <cuda_runtime.h>
#include <cuda_bf16.h>
#include <cstdint>

#define N_B 4096
#define NTHREADS 512

// ---------------- smem layout (bytes) ----------------
#define SM_BH    0        // 32768  W2_hi  [n][k] bf16, swizzled
#define SM_BL    32768    // 32768  W2_lo
#define SM_AH    65536    // 65536  A_hi   [m=256][k] bf16, swizzled
#define SM_AL    131072   // 65536  A_lo
#define SM_W1    196608   // 4096   W1 [k][col] f32
#define SM_EPI   200704   // 2048   per-col float4 {b2, w3_0, w3_1, 0}
#define SM_B1    202752   // 512
#define SM_FEAT  203264   // 8192   feat[256][8] f32
#define SM_B3    211456   // 8
#define SMEM_TOTAL 211472

// ---------------- helpers ----------------
__device__ __forceinline__ uint32_t smem_u32_of(const void* p) {
    uint32_t a;
    asm("{ .reg .u64 t; cvta.to.shared.u64 t, %1; cvt.u32.u64 %0, t; }" : "=r"(a) : "l"(p));
    return a;
}
__device__ __forceinline__ unsigned long long pack_dup(float v) {
    unsigned long long r; asm("mov.b64 %0, {%1, %1};" : "=l"(r) : "f"(v)); return r;
}
__device__ __forceinline__ unsigned long long ffma2(unsigned long long a, unsigned long long b,
                                                    unsigned long long c) {
    unsigned long long d; asm("fma.rn.f32x2 %0, %1, %2, %3;" : "=l"(d) : "l"(a), "l"(b), "l"(c));
    return d;
}
__device__ __forceinline__ float2 unpack2(unsigned long long v) {
    float2 r; asm("mov.b64 {%0, %1}, %2;" : "=f"(r.x), "=f"(r.y) : "l"(v)); return r;
}
__device__ __forceinline__ uint32_t cvt2bf(float hi, float lo) {  // hi->upper16, lo->lower16
    uint32_t r; asm("cvt.rn.bf16x2.f32 %0, %1, %2;" : "=r"(r) : "f"(hi), "f"(lo)); return r;
}
__device__ __forceinline__ void ldsm4(uint32_t* r, uint32_t addr) {
    asm volatile("ldmatrix.sync.aligned.m8n8.x4.shared.b16 {%0,%1,%2,%3}, [%4];"
                 : "=r"(r[0]), "=r"(r[1]), "=r"(r[2]), "=r"(r[3]) : "r"(addr));
}
__device__ __forceinline__ void mma16816(float* d, const uint32_t* a, uint32_t b0, uint32_t b1) {
    asm volatile("mma.sync.aligned.m16n8k16.row.col.f32.bf16.bf16.f32 "
                 "{%0,%1,%2,%3}, {%4,%5,%6,%7}, {%8,%9}, {%0,%1,%2,%3};"
                 : "+f"(d[0]), "+f"(d[1]), "+f"(d[2]), "+f"(d[3])
                 : "r"(a[0]), "r"(a[1]), "r"(a[2]), "r"(a[3]), "r"(b0), "r"(b1));
}

// per-warp conv: features + L1 + bf16 hi/lo split for this warp's 16 rows.
template <int DIR>
__device__ __forceinline__ void conv_warp(char* sm, const float* __restrict__ x,
                                          const float* __restrict__ t, int b,
                                          int wid, int lane)
{
    const int r0 = wid * 16;
    float* sFeat = (float*)(sm + SM_FEAT);
    if (lane < 16) {
        const int m = r0 + lane, i = m;
        const float* xb = x + (size_t)b * 514;
        const float2 xi  = *(const float2*)(xb + i * 2);
        const float2 xi1 = *(const float2*)(xb + i * 2 + 2);
        const float2 pt  = *(const float2*)(xb + 512);
        const float tb = t[b];
        float* f = sFeat + m * 8;
        if (DIR == 0) { f[0]=xi1.x; f[1]=xi1.y; f[2]=tb; f[3]=xi.x;  f[4]=xi.y;  f[5]=(float)(i+1)*(1.f/256.f); }
        else          { f[0]=xi.x;  f[1]=xi.y;  f[2]=tb; f[3]=xi1.x; f[4]=xi1.y; f[5]=(float)i*(1.f/256.f); }
        f[6]=pt.x; f[7]=pt.y;
    }
    __syncwarp();

    const float* sW1 = (const float*)(sm + SM_W1);
    unsigned long long w1p[16];
    #pragma unroll
    for (int k = 0; k < 8; k++) {
        const ulonglong2 q = *(const ulonglong2*)(sW1 + k * 128 + lane * 4);
        w1p[2 * k] = q.x; w1p[2 * k + 1] = q.y;
    }
    const ulonglong2 b1q = *(const ulonglong2*)((const float*)(sm + SM_B1) + lane * 4);

    char* ah = sm + SM_AH;
    char* al = sm + SM_AL;
    const uint32_t chk = lane >> 1;
    const uint32_t halfsel = (lane & 1) * 8;
    #pragma unroll 4
    for (int j = 0; j < 16; j++) {
        const int m = r0 + j;
        const float* f = sFeat + m * 8;
        const float4 fa = *(const float4*)(f);
        const float4 fb = *(const float4*)(f + 4);
        unsigned long long a0 = b1q.x, a1 = b1q.y;
        a0 = ffma2(pack_dup(fa.x), w1p[0],  a0); a1 = ffma2(pack_dup(fa.x), w1p[1],  a1);
        a0 = ffma2(pack_dup(fa.y), w1p[2],  a0); a1 = ffma2(pack_dup(fa.y), w1p[3],  a1);
        a0 = ffma2(pack_dup(fa.z), w1p[4],  a0); a1 = ffma2(pack_dup(fa.z), w1p[5],  a1);
        a0 = ffma2(pack_dup(fa.w), w1p[6],  a0); a1 = ffma2(pack_dup(fa.w), w1p[7],  a1);
        a0 = ffma2(pack_dup(fb.x), w1p[8],  a0); a1 = ffma2(pack_dup(fb.x), w1p[9],  a1);
        a0 = ffma2(pack_dup(fb.y), w1p[10], a0); a1 = ffma2(pack_dup(fb.y), w1p[11], a1);
        a0 = ffma2(pack_dup(fb.z), w1p[12], a0); a1 = ffma2(pack_dup(fb.z), w1p[13], a1);
        a0 = ffma2(pack_dup(fb.w), w1p[14], a0); a1 = ffma2(pack_dup(fb.w), w1p[15], a1);
        const float2 v01 = unpack2(a0), v23 = unpack2(a1);
        const float v0 = fmaxf(v01.x, 0.f), v1 = fmaxf(v01.y, 0.f);
        const float v2 = fmaxf(v23.x, 0.f), v3 = fmaxf(v23.y, 0.f);
        const uint32_t h0 = cvt2bf(v1, v0), h1 = cvt2bf(v3, v2);
        const float g0 = __uint_as_float(h0 << 16), g1 = __uint_as_float(h0 & 0xffff0000u);
        const float g2 = __uint_as_float(h1 << 16), g3 = __uint_as_float(h1 & 0xffff0000u);
        const uint32_t l0 = cvt2bf(v1 - g1, v0 - g0), l1 = cvt2bf(v3 - g3, v2 - g2);
        const uint32_t off = (uint32_t)m * 256 + (((chk ^ (uint32_t)(m & 7)) << 4)) + halfsel;
        *(uint2*)(ah + off) = make_uint2(h0, h1);
        *(uint2*)(al + off) = make_uint2(l0, l1);
    }
    __syncwarp();
}

template <int DIR>
__global__ void __launch_bounds__(NTHREADS, 1)
fused_kernel(const float* __restrict__ x, const float* __restrict__ t,
             const float* __restrict__ W1, const float* __restrict__ b1v,
             const float* __restrict__ W2, const float* __restrict__ b2v,
             const float* __restrict__ W3, const float* __restrict__ b3v,
             float* __restrict__ out, int ntiles)
{
    extern __shared__ __align__(1024) char sm[];
    const int tid = threadIdx.x, wid = tid >> 5, lane = tid & 31;
    const uint32_t smb = smem_u32_of(sm);

    // ---- prologue: split + transpose W2 into [n][k] hi/lo, small weights ----
    for (int idx = tid; idx < 16384; idx += NTHREADS) {
        const int n = idx >> 7, k = idx & 127;
        const float w = W2[k * 128 + n];
        const __nv_bfloat16 hb = __float2bfloat16(w);
        const __nv_bfloat16 lb = __float2bfloat16(w - __bfloat162float(hb));
        const uint32_t off = (uint32_t)n * 256 + ((((uint32_t)(k >> 3) ^ (uint32_t)(n & 7)) << 4)) +
                             (uint32_t)(k & 7) * 2;
        *(__nv_bfloat16*)(sm + SM_BH + off) = hb;
        *(__nv_bfloat16*)(sm + SM_BL + off) = lb;
    }
    float* sW1 = (float*)(sm + SM_W1);
    for (int idx = tid; idx < 1024; idx += NTHREADS) sW1[idx] = W1[idx];
    if (tid < 128) {
        float4 e; e.x = b2v[tid]; e.y = W3[tid * 2]; e.z = W3[tid * 2 + 1]; e.w = 0.f;
        ((float4*)(sm + SM_EPI))[tid] = e;
        ((float*)(sm + SM_B1))[tid] = b1v[tid];
    }
    if (tid == 0) ((float2*)(sm + SM_B3))[0] = make_float2(b3v[0], b3v[1]);
    __syncthreads();

    const float2 b3 = ((const float2*)(sm + SM_B3))[0];

    // ldmatrix lane-address components
    const uint32_t rA = (uint32_t)(wid * 16) + (uint32_t)(lane & 15);
    const uint32_t rowA_off = rA * 256;
    const uint32_t rxA = rA & 7;
    const uint32_t cA_bit = (uint32_t)(lane >> 4);
    const uint32_t nB = (uint32_t)(lane & 7) + (uint32_t)((lane & 16) >> 1);
    const uint32_t rowB_off = nB * 256;
    const uint32_t rxB = nB & 7;
    const uint32_t cB_bit = (uint32_t)((lane >> 3) & 1);

    const uint32_t aH = smb + SM_AH, aL = smb + SM_AL;
    const uint32_t bH = smb + SM_BH, bL = smb + SM_BL;
    const float4* epi = (const float4*)(sm + SM_EPI);

    // Warp-staggered tile order: warp w starts (w*K/16) iterations in, so the
    // conv/mma/epilogue phases of the 16 independent warps de-phase and the
    // tensor pipe stays fed. Each warp still covers exactly the same tile set.
    const int K = (ntiles + gridDim.x - 1) / (int)gridDim.x;
    const int off0 = (wid * K) >> 4;

    for (int k = 0; k < K; k++) {
        int kk = k + off0; if (kk >= K) kk -= K;
        const int tt = (int)blockIdx.x + kk * (int)gridDim.x;
        if (tt >= ntiles) continue;
        const int b = tt;                 // one 256-row tile per batch
        conv_warp<DIR>(sm, x, t, b, wid, lane);

        float acc[16][4];
        #pragma unroll
        for (int nb = 0; nb < 16; nb++)
            { acc[nb][0] = 0.f; acc[nb][1] = 0.f; acc[nb][2] = 0.f; acc[nb][3] = 0.f; }

        #pragma unroll 2
        for (int kb = 0; kb < 8; kb++) {
            const uint32_t cA = (uint32_t)(2 * kb) + cA_bit;
            const uint32_t offA = rowA_off + ((cA ^ rxA) << 4);
            uint32_t ah[4], al[4];
            ldsm4(ah, aH + offA);
            ldsm4(al, aL + offA);
            const uint32_t cB = (uint32_t)(2 * kb) + cB_bit;
            const uint32_t offB0 = rowB_off + ((cB ^ rxB) << 4);
            #pragma unroll
            for (int nb2 = 0; nb2 < 8; nb2++) {
                uint32_t bh[4], bl[4];
                const uint32_t offB = offB0 + (uint32_t)nb2 * 4096;
                ldsm4(bh, bH + offB);
                ldsm4(bl, bL + offB);
                mma16816(acc[2 * nb2],     ah, bh[0], bh[1]);
                mma16816(acc[2 * nb2],     ah, bl[0], bl[1]);
                mma16816(acc[2 * nb2],     al, bh[0], bh[1]);
                mma16816(acc[2 * nb2 + 1], ah, bh[2], bh[3]);
                mma16816(acc[2 * nb2 + 1], ah, bl[2], bl[3]);
                mma16816(acc[2 * nb2 + 1], al, bh[2], bh[3]);
            }
        }

        // ---- epilogue: relu(acc + b2) @ W3, 4-lane reduce, store ----
        float pa0 = 0.f, pa1 = 0.f, pb0 = 0.f, pb1 = 0.f;
        #pragma unroll
        for (int nb = 0; nb < 16; nb++) {
            const int col0 = nb * 8 + 2 * (lane & 3);
            const float4 e0 = epi[col0], e1 = epi[col0 + 1];
            float v;
            v = fmaxf(acc[nb][0] + e0.x, 0.f); pa0 += v * e0.y; pa1 += v * e0.z;
            v = fmaxf(acc[nb][1] + e1.x, 0.f); pa0 += v * e1.y; pa1 += v * e1.z;
            v = fmaxf(acc[nb][2] + e0.x, 0.f); pb0 += v * e0.y; pb1 += v * e0.z;
            v = fmaxf(acc[nb][3] + e1.x, 0.f); pb0 += v * e1.y; pb1 += v * e1.z;
        }
        #pragma unroll
        for (int s = 1; s <= 2; s <<= 1) {
            pa0 += __shfl_xor_sync(0xffffffffu, pa0, s);
            pa1 += __shfl_xor_sync(0xffffffffu, pa1, s);
            pb0 += __shfl_xor_sync(0xffffffffu, pb0, s);
            pb1 += __shfl_xor_sync(0xffffffffu, pb1, s);
        }
        if ((lane & 3) == 0) {
            const int q = lane >> 2;
            const int m1 = wid * 16 + q;      // rows m1 and m1+8
            const int i1 = m1, i2 = m1 + 8;
            float* ob = out + (size_t)b * 512;
            if (DIR == 0) {
                if (m1 == 0) *(float2*)ob = make_float2(0.f, 0.f);
                if (i1 < 255) *(float2*)(ob + (i1 + 1) * 2) = make_float2(pa0 + b3.x, pa1 + b3.y);
                if (i2 < 255) *(float2*)(ob + (i2 + 1) * 2) = make_float2(pb0 + b3.x, pb1 + b3.y);
            } else {
                if (i1 < 255) {
                    float2* o = (float2*)(ob + i1 * 2);
                    const float2 v = *o; *o = make_float2(v.x + pa0 + b3.x, v.y + pa1 + b3.y);
                }
                if (i2 < 255) {
                    float2* o = (float2*)(ob + i2 * 2);
                    const float2 v = *o; *o = make_float2(v.x + pb0 + b3.x, v.y + pb1 + b3.y);
                }
            }
        }
        __syncwarp();
    }
}

// ---------------- init MLP (3->128->128->2, 4096 rows) ----------------
__global__ void __launch_bounds__(128)
init_kernel(const float* __restrict__ x, const float* __restrict__ t,
            const float* __restrict__ W1, const float* __restrict__ b1,
            const float* __restrict__ W2, const float* __restrict__ b2,
            const float* __restrict__ W3, const float* __restrict__ b3,
            float* __restrict__ out, int nrows)
{
    extern __shared__ float ism[];
    float* sW2 = ism;           // 16384
    float* sh  = ism + 16384;   // 128
    float* red = ism + 16512;   // 8
    const int tid = threadIdx.x;
    for (int i = tid; i < 16384; i += 128) sW2[i] = W2[i];
    const float w10 = W1[tid], w11 = W1[128 + tid], w12 = W1[256 + tid];
    const float bb1 = b1[tid], bb2 = b2[tid];
    const float w30 = W3[tid * 2], w31 = W3[tid * 2 + 1];
    __syncthreads();
    for (int r = blockIdx.x; r < nrows; r += gridDim.x) {
        const float2 x0 = *(const float2*)(x + (size_t)r * 514);
        const float tb = t[r];
        sh[tid] = fmaxf(bb1 + x0.x * w10 + x0.y * w11 + tb * w12, 0.f);
        __syncthreads();
        float a = bb2;
        #pragma unroll 8
        for (int k = 0; k < 128; k++) a += sh[k] * sW2[k * 128 + tid];
        a = fmaxf(a, 0.f);
        float p0 = a * w30, p1 = a * w31;
        #pragma unroll
        for (int s = 16; s; s >>= 1) {
            p0 += __shfl_xor_sync(0xffffffffu, p0, s);
            p1 += __shfl_xor_sync(0xffffffffu, p1, s);
        }
        if ((tid & 31) == 0) { red[tid >> 5] = p0; red[4 + (tid >> 5)] = p1; }
        __syncthreads();
        if (tid == 0) {
            const float q0 = red[0] + red[1] + red[2] + red[3] + b3[0];
            const float q1 = red[4] + red[5] + red[6] + red[7] + b3[1];
            float2* o = (float2*)(out + (size_t)r * 512);
            const float2 v = *o; *o = make_float2(v.x + q0, v.y + q1);
        }
        __syncthreads();
    }
}

extern "C" void kernel_launch(void* const* d_in, const int* in_sizes, int n_in,
                              void* d_out, int out_size)
{
    (void)in_sizes; (void)n_in; (void)out_size;
    const float* x = (const float*)d_in[0];
    const float* t = (const float*)d_in[1];
    float* out = (float*)d_out;

    static int grid = 0;
    if (grid == 0) {
        int dev = 0, sms = 148;
        cudaGetDevice(&dev);
        cudaDeviceGetAttribute(&sms, cudaDevAttrMultiProcessorCount, dev);
        grid = sms;
        cudaFuncSetAttribute(fused_kernel<0>, cudaFuncAttributeMaxDynamicSharedMemorySize, SMEM_TOTAL);
        cudaFuncSetAttribute(fused_kernel<1>, cudaFuncAttributeMaxDynamicSharedMemorySize, SMEM_TOTAL);
        cudaFuncSetAttribute(init_kernel, cudaFuncAttributeMaxDynamicSharedMemorySize, 16520 * 4);
    }

    const int ntiles = N_B;       // one 256-row tile per batch

    fused_kernel<0><<<grid, NTHREADS, SMEM_TOTAL>>>(x, t,
        (const float*)d_in[2], (const float*)d_in[3], (const float*)d_in[4],
        (const float*)d_in[5], (const float*)d_in[6], (const float*)d_in[7], out, ntiles);
    fused_kernel<1><<<grid, NTHREADS, SMEM_TOTAL>>>(x, t,
        (const float*)d_in[8], (const float*)d_in[9], (const float*)d_in[10],
        (const float*)d_in[11], (const float*)d_in[12], (const float*)d_in[13], out, ntiles);
    init_kernel<<<128, 128, 16520 * 4>>>(x, t,
        (const float*)d_in[14], (const float*)d_in[15], (const float*)d_in[16],
        (const float*)d_in[17], (const float*)d_in[18], (const float*)d_in[19], out, N_B);
}

// round 9
// speedup vs baseline: 1.3494x; 1.2759x over previous
#include <cuda_runtime.h>
#include <cuda_fp16.h>
#include <cstdint>

#define N_B 4096
#define NTHREADS 512

// ---------------- smem layout (bytes) ----------------
#define SM_BH    0        // 32768  W2_hi  [n][k] fp16, swizzled
#define SM_BL    32768    // 32768  W2_lo  [n][k] fp16, swizzled
#define SM_A     65536    // 65536  A      [m=256][k] fp16, swizzled
#define SM_W1    131072   // 4096   W1 [k][col] f32
#define SM_EPI   135168   // 2048   per-col float4 {b2, w3_0, w3_1, 0}
#define SM_B1    137216   // 512
#define SM_FEAT  137728   // 8192   feat[256][8] f32
#define SM_B3    145920   // 8
#define SMEM_TOTAL 145984

// ---------------- helpers ----------------
__device__ __forceinline__ uint32_t smem_u32_of(const void* p) {
    uint32_t a;
    asm("{ .reg .u64 t; cvta.to.shared.u64 t, %1; cvt.u32.u64 %0, t; }" : "=r"(a) : "l"(p));
    return a;
}
__device__ __forceinline__ unsigned long long pack_dup(float v) {
    unsigned long long r; asm("mov.b64 %0, {%1, %1};" : "=l"(r) : "f"(v)); return r;
}
__device__ __forceinline__ unsigned long long ffma2(unsigned long long a, unsigned long long b,
                                                    unsigned long long c) {
    unsigned long long d; asm("fma.rn.f32x2 %0, %1, %2, %3;" : "=l"(d) : "l"(a), "l"(b), "l"(c));
    return d;
}
__device__ __forceinline__ float2 unpack2(unsigned long long v) {
    float2 r; asm("mov.b64 {%0, %1}, %2;" : "=f"(r.x), "=f"(r.y) : "l"(v)); return r;
}
__device__ __forceinline__ uint32_t cvt2hf(float hi, float lo) {  // hi->upper16, lo->lower16
    uint32_t r; asm("cvt.rn.f16x2.f32 %0, %1, %2;" : "=r"(r) : "f"(hi), "f"(lo)); return r;
}
__device__ __forceinline__ void ldsm4(uint32_t* r, uint32_t addr) {
    asm volatile("ldmatrix.sync.aligned.m8n8.x4.shared.b16 {%0,%1,%2,%3}, [%4];"
                 : "=r"(r[0]), "=r"(r[1]), "=r"(r[2]), "=r"(r[3]) : "r"(addr));
}
__device__ __forceinline__ void mma16816(float* d, const uint32_t* a, uint32_t b0, uint32_t b1) {
    asm volatile("mma.sync.aligned.m16n8k16.row.col.f32.f16.f16.f32 "
                 "{%0,%1,%2,%3}, {%4,%5,%6,%7}, {%8,%9}, {%0,%1,%2,%3};"
                 : "+f"(d[0]), "+f"(d[1]), "+f"(d[2]), "+f"(d[3])
                 : "r"(a[0]), "r"(a[1]), "r"(a[2]), "r"(a[3]), "r"(b0), "r"(b1));
}

// per-warp conv: features + L1 + fp16 convert for this warp's 16 rows.
template <int DIR>
__device__ __forceinline__ void conv_warp(char* sm, const float* __restrict__ x,
                                          const float* __restrict__ t, int b,
                                          int wid, int lane)
{
    const int r0 = wid * 16;
    float* sFeat = (float*)(sm + SM_FEAT);
    if (lane < 16) {
        const int m = r0 + lane, i = m;
        const float* xb = x + (size_t)b * 514;
        const float2 xi  = *(const float2*)(xb + i * 2);
        const float2 xi1 = *(const float2*)(xb + i * 2 + 2);
        const float2 pt  = *(const float2*)(xb + 512);
        const float tb = t[b];
        float* f = sFeat + m * 8;
        if (DIR == 0) { f[0]=xi1.x; f[1]=xi1.y; f[2]=tb; f[3]=xi.x;  f[4]=xi.y;  f[5]=(float)(i+1)*(1.f/256.f); }
        else          { f[0]=xi.x;  f[1]=xi.y;  f[2]=tb; f[3]=xi1.x; f[4]=xi1.y; f[5]=(float)i*(1.f/256.f); }
        f[6]=pt.x; f[7]=pt.y;
    }
    __syncwarp();

    const float* sW1 = (const float*)(sm + SM_W1);
    unsigned long long w1p[16];
    #pragma unroll
    for (int k = 0; k < 8; k++) {
        const ulonglong2 q = *(const ulonglong2*)(sW1 + k * 128 + lane * 4);
        w1p[2 * k] = q.x; w1p[2 * k + 1] = q.y;
    }
    const ulonglong2 b1q = *(const ulonglong2*)((const float*)(sm + SM_B1) + lane * 4);

    char* sa = sm + SM_A;
    const uint32_t chk = lane >> 1;
    const uint32_t halfsel = (lane & 1) * 8;
    #pragma unroll 4
    for (int j = 0; j < 16; j++) {
        const int m = r0 + j;
        const float* f = sFeat + m * 8;
        const float4 fa = *(const float4*)(f);
        const float4 fb = *(const float4*)(f + 4);
        unsigned long long a0 = b1q.x, a1 = b1q.y;
        a0 = ffma2(pack_dup(fa.x), w1p[0],  a0); a1 = ffma2(pack_dup(fa.x), w1p[1],  a1);
        a0 = ffma2(pack_dup(fa.y), w1p[2],  a0); a1 = ffma2(pack_dup(fa.y), w1p[3],  a1);
        a0 = ffma2(pack_dup(fa.z), w1p[4],  a0); a1 = ffma2(pack_dup(fa.z), w1p[5],  a1);
        a0 = ffma2(pack_dup(fa.w), w1p[6],  a0); a1 = ffma2(pack_dup(fa.w), w1p[7],  a1);
        a0 = ffma2(pack_dup(fb.x), w1p[8],  a0); a1 = ffma2(pack_dup(fb.x), w1p[9],  a1);
        a0 = ffma2(pack_dup(fb.y), w1p[10], a0); a1 = ffma2(pack_dup(fb.y), w1p[11], a1);
        a0 = ffma2(pack_dup(fb.z), w1p[12], a0); a1 = ffma2(pack_dup(fb.z), w1p[13], a1);
        a0 = ffma2(pack_dup(fb.w), w1p[14], a0); a1 = ffma2(pack_dup(fb.w), w1p[15], a1);
        const float2 v01 = unpack2(a0), v23 = unpack2(a1);
        const float v0 = fmaxf(v01.x, 0.f), v1 = fmaxf(v01.y, 0.f);
        const float v2 = fmaxf(v23.x, 0.f), v3 = fmaxf(v23.y, 0.f);
        const uint32_t h0 = cvt2hf(v1, v0), h1 = cvt2hf(v3, v2);
        const uint32_t off = (uint32_t)m * 256 + (((chk ^ (uint32_t)(m & 7)) << 4)) + halfsel;
        *(uint2*)(sa + off) = make_uint2(h0, h1);
    }
    __syncwarp();
}

template <int DIR>
__global__ void __launch_bounds__(NTHREADS, 1)
fused_kernel(const float* __restrict__ x, const float* __restrict__ t,
             const float* __restrict__ W1, const float* __restrict__ b1v,
             const float* __restrict__ W2, const float* __restrict__ b2v,
             const float* __restrict__ W3, const float* __restrict__ b3v,
             float* __restrict__ out, int ntiles)
{
    extern __shared__ __align__(1024) char sm[];
    const int tid = threadIdx.x, wid = tid >> 5, lane = tid & 31;
    const uint32_t smb = smem_u32_of(sm);

    // ---- prologue: split + transpose W2 into [n][k] fp16 hi/lo, small weights ----
    for (int idx = tid; idx < 16384; idx += NTHREADS) {
        const int n = idx >> 7, k = idx & 127;
        const float w = W2[k * 128 + n];
        const __half hb = __float2half_rn(w);
        const __half lb = __float2half_rn(w - __half2float(hb));
        const uint32_t off = (uint32_t)n * 256 + ((((uint32_t)(k >> 3) ^ (uint32_t)(n & 7)) << 4)) +
                             (uint32_t)(k & 7) * 2;
        *(__half*)(sm + SM_BH + off) = hb;
        *(__half*)(sm + SM_BL + off) = lb;
    }
    float* sW1 = (float*)(sm + SM_W1);
    for (int idx = tid; idx < 1024; idx += NTHREADS) sW1[idx] = W1[idx];
    if (tid < 128) {
        float4 e; e.x = b2v[tid]; e.y = W3[tid * 2]; e.z = W3[tid * 2 + 1]; e.w = 0.f;
        ((float4*)(sm + SM_EPI))[tid] = e;
        ((float*)(sm + SM_B1))[tid] = b1v[tid];
    }
    if (tid == 0) ((float2*)(sm + SM_B3))[0] = make_float2(b3v[0], b3v[1]);
    __syncthreads();

    const float2 b3 = ((const float2*)(sm + SM_B3))[0];

    // ldmatrix lane-address components
    const uint32_t rA = (uint32_t)(wid * 16) + (uint32_t)(lane & 15);
    const uint32_t rowA_off = rA * 256;
    const uint32_t rxA = rA & 7;
    const uint32_t cA_bit = (uint32_t)(lane >> 4);
    const uint32_t nB = (uint32_t)(lane & 7) + (uint32_t)((lane & 16) >> 1);
    const uint32_t rowB_off = nB * 256;
    const uint32_t rxB = nB & 7;
    const uint32_t cB_bit = (uint32_t)((lane >> 3) & 1);

    const uint32_t aA = smb + SM_A;
    const uint32_t bH = smb + SM_BH, bL = smb + SM_BL;
    const float4* epi = (const float4*)(sm + SM_EPI);

    // Warp-staggered tile order (cheap, keeps warps de-phased).
    const int K = (ntiles + gridDim.x - 1) / (int)gridDim.x;
    const int off0 = (wid * K) >> 4;

    for (int k = 0; k < K; k++) {
        int kk = k + off0; if (kk >= K) kk -= K;
        const int tt = (int)blockIdx.x + kk * (int)gridDim.x;
        if (tt >= ntiles) continue;
        const int b = tt;                 // one 256-row tile per batch
        conv_warp<DIR>(sm, x, t, b, wid, lane);

        float acc[16][4];
        #pragma unroll
        for (int nb = 0; nb < 16; nb++)
            { acc[nb][0] = 0.f; acc[nb][1] = 0.f; acc[nb][2] = 0.f; acc[nb][3] = 0.f; }

        #pragma unroll 2
        for (int kb = 0; kb < 8; kb++) {
            const uint32_t cA = (uint32_t)(2 * kb) + cA_bit;
            const uint32_t offA = rowA_off + ((cA ^ rxA) << 4);
            uint32_t a[4];
            ldsm4(a, aA + offA);
            const uint32_t cB = (uint32_t)(2 * kb) + cB_bit;
            const uint32_t offB0 = rowB_off + ((cB ^ rxB) << 4);
            #pragma unroll
            for (int nb2 = 0; nb2 < 8; nb2++) {
                uint32_t bh[4], bl[4];
                const uint32_t offB = offB0 + (uint32_t)nb2 * 4096;
                ldsm4(bh, bH + offB);
                ldsm4(bl, bL + offB);
                mma16816(acc[2 * nb2],     a, bh[0], bh[1]);
                mma16816(acc[2 * nb2],     a, bl[0], bl[1]);
                mma16816(acc[2 * nb2 + 1], a, bh[2], bh[3]);
                mma16816(acc[2 * nb2 + 1], a, bl[2], bl[3]);
            }
        }

        // ---- epilogue: relu(acc + b2) @ W3, 4-lane reduce, store ----
        float pa0 = 0.f, pa1 = 0.f, pb0 = 0.f, pb1 = 0.f;
        #pragma unroll
        for (int nb = 0; nb < 16; nb++) {
            const int col0 = nb * 8 + 2 * (lane & 3);
            const float4 e0 = epi[col0], e1 = epi[col0 + 1];
            float v;
            v = fmaxf(acc[nb][0] + e0.x, 0.f); pa0 += v * e0.y; pa1 += v * e0.z;
            v = fmaxf(acc[nb][1] + e1.x, 0.f); pa0 += v * e1.y; pa1 += v * e1.z;
            v = fmaxf(acc[nb][2] + e0.x, 0.f); pb0 += v * e0.y; pb1 += v * e0.z;
            v = fmaxf(acc[nb][3] + e1.x, 0.f); pb0 += v * e1.y; pb1 += v * e1.z;
        }
        #pragma unroll
        for (int s = 1; s <= 2; s <<= 1) {
            pa0 += __shfl_xor_sync(0xffffffffu, pa0, s);
            pa1 += __shfl_xor_sync(0xffffffffu, pa1, s);
            pb0 += __shfl_xor_sync(0xffffffffu, pb0, s);
            pb1 += __shfl_xor_sync(0xffffffffu, pb1, s);
        }
        if ((lane & 3) == 0) {
            const int q = lane >> 2;
            const int m1 = wid * 16 + q;      // rows m1 and m1+8
            const int i1 = m1, i2 = m1 + 8;
            float* ob = out + (size_t)b * 512;
            if (DIR == 0) {
                if (m1 == 0) *(float2*)ob = make_float2(0.f, 0.f);
                if (i1 < 255) *(float2*)(ob + (i1 + 1) * 2) = make_float2(pa0 + b3.x, pa1 + b3.y);
                if (i2 < 255) *(float2*)(ob + (i2 + 1) * 2) = make_float2(pb0 + b3.x, pb1 + b3.y);
            } else {
                if (i1 < 255) {
                    float2* o = (float2*)(ob + i1 * 2);
                    const float2 v = *o; *o = make_float2(v.x + pa0 + b3.x, v.y + pa1 + b3.y);
                }
                if (i2 < 255) {
                    float2* o = (float2*)(ob + i2 * 2);
                    const float2 v = *o; *o = make_float2(v.x + pb0 + b3.x, v.y + pb1 + b3.y);
                }
            }
        }
        __syncwarp();
    }
}

// ---------------- init MLP (3->128->128->2, 4096 rows) ----------------
__global__ void __launch_bounds__(128)
init_kernel(const float* __restrict__ x, const float* __restrict__ t,
            const float* __restrict__ W1, const float* __restrict__ b1,
            const float* __restrict__ W2, const float* __restrict__ b2,
            const float* __restrict__ W3, const float* __restrict__ b3,
            float* __restrict__ out, int nrows)
{
    extern __shared__ float ism[];
    float* sW2 = ism;           // 16384
    float* sh  = ism + 16384;   // 128
    float* red = ism + 16512;   // 8
    const int tid = threadIdx.x;
    for (int i = tid; i < 16384; i += 128) sW2[i] = W2[i];
    const float w10 = W1[tid], w11 = W1[128 + tid], w12 = W1[256 + tid];
    const float bb1 = b1[tid], bb2 = b2[tid];
    const float w30 = W3[tid * 2], w31 = W3[tid * 2 + 1];
    __syncthreads();
    for (int r = blockIdx.x; r < nrows; r += gridDim.x) {
        const float2 x0 = *(const float2*)(x + (size_t)r * 514);
        const float tb = t[r];
        sh[tid] = fmaxf(bb1 + x0.x * w10 + x0.y * w11 + tb * w12, 0.f);
        __syncthreads();
        float a = bb2;
        #pragma unroll 8
        for (int k = 0; k < 128; k++) a += sh[k] * sW2[k * 128 + tid];
        a = fmaxf(a, 0.f);
        float p0 = a * w30, p1 = a * w31;
        #pragma unroll
        for (int s = 16; s; s >>= 1) {
            p0 += __shfl_xor_sync(0xffffffffu, p0, s);
            p1 += __shfl_xor_sync(0xffffffffu, p1, s);
        }
        if ((tid & 31) == 0) { red[tid >> 5] = p0; red[4 + (tid >> 5)] = p1; }
        __syncthreads();
        if (tid == 0) {
            const float q0 = red[0] + red[1] + red[2] + red[3] + b3[0];
            const float q1 = red[4] + red[5] + red[6] + red[7] + b3[1];
            float2* o = (float2*)(out + (size_t)r * 512);
            const float2 v = *o; *o = make_float2(v.x + q0, v.y + q1);
        }
        __syncthreads();
    }
}

extern "C" void kernel_launch(void* const* d_in, const int* in_sizes, int n_in,
                              void* d_out, int out_size)
{
    (void)in_sizes; (void)n_in; (void)out_size;
    const float* x = (const float*)d_in[0];
    const float* t = (const float*)d_in[1];
    float* out = (float*)d_out;

    static int grid = 0;
    if (grid == 0) {
        int dev = 0, sms = 148;
        cudaGetDevice(&dev);
        cudaDeviceGetAttribute(&sms, cudaDevAttrMultiProcessorCount, dev);
        grid = sms;
        cudaFuncSetAttribute(fused_kernel<0>, cudaFuncAttributeMaxDynamicSharedMemorySize, SMEM_TOTAL);
        cudaFuncSetAttribute(fused_kernel<1>, cudaFuncAttributeMaxDynamicSharedMemorySize, SMEM_TOTAL);
        cudaFuncSetAttribute(init_kernel, cudaFuncAttributeMaxDynamicSharedMemorySize, 16520 * 4);
    }

    const int ntiles = N_B;       // one 256-row tile per batch

    fused_kernel<0><<<grid, NTHREADS, SMEM_TOTAL>>>(x, t,
        (const float*)d_in[2], (const float*)d_in[3], (const float*)d_in[4],
        (const float*)d_in[5], (const float*)d_in[6], (const float*)d_in[7], out, ntiles);
    fused_kernel<1><<<grid, NTHREADS, SMEM_TOTAL>>>(x, t,
        (const float*)d_in[8], (const float*)d_in[9], (const float*)d_in[10],
        (const float*)d_in[11], (const float*)d_in[12], (const float*)d_in[13], out, ntiles);
    init_kernel<<<304, 128, 16520 * 4>>>(x, t,
        (const float*)d_in[14], (const float*)d_in[15], (const float*)d_in[16],
        (const float*)d_in[17], (const float*)d_in[18], (const float*)d_in[19], out, N_B);
}

// round 10
// speedup vs baseline: 1.7595x; 1.3039x over previous
#include <cuda_runtime.h>
#include <cuda_fp16.h>
#include <cstdint>

#define N_B 4096
#define NTHREADS 512

// ---------------- smem layout (bytes) ----------------
#define SM_B     0        // 32768  W2 [n][k] fp16, swizzled
#define SM_A     32768    // 65536  A  [m=256][k] fp16, swizzled
#define SM_W1    98304    // 4096   W1 [k][col] f32
#define SM_EPI   102400   // 2048   per-col float4 {b2, w3_0, w3_1, 0}
#define SM_B1    104448   // 512
#define SM_FEAT  104960   // 8192   feat[256][8] f32
#define SM_B3    113152   // 8
#define SMEM_TOTAL 113216

// ---------------- helpers ----------------
__device__ __forceinline__ uint32_t smem_u32_of(const void* p) {
    uint32_t a;
    asm("{ .reg .u64 t; cvta.to.shared.u64 t, %1; cvt.u32.u64 %0, t; }" : "=r"(a) : "l"(p));
    return a;
}
__device__ __forceinline__ unsigned long long pack_dup(float v) {
    unsigned long long r; asm("mov.b64 %0, {%1, %1};" : "=l"(r) : "f"(v)); return r;
}
__device__ __forceinline__ unsigned long long ffma2(unsigned long long a, unsigned long long b,
                                                    unsigned long long c) {
    unsigned long long d; asm("fma.rn.f32x2 %0, %1, %2, %3;" : "=l"(d) : "l"(a), "l"(b), "l"(c));
    return d;
}
__device__ __forceinline__ float2 unpack2(unsigned long long v) {
    float2 r; asm("mov.b64 {%0, %1}, %2;" : "=f"(r.x), "=f"(r.y) : "l"(v)); return r;
}
__device__ __forceinline__ uint32_t cvt2hf(float hi, float lo) {  // hi->upper16, lo->lower16
    uint32_t r; asm("cvt.rn.f16x2.f32 %0, %1, %2;" : "=r"(r) : "f"(hi), "f"(lo)); return r;
}
__device__ __forceinline__ void ldsm4(uint32_t* r, uint32_t addr) {
    asm volatile("ldmatrix.sync.aligned.m8n8.x4.shared.b16 {%0,%1,%2,%3}, [%4];"
                 : "=r"(r[0]), "=r"(r[1]), "=r"(r[2]), "=r"(r[3]) : "r"(addr));
}
__device__ __forceinline__ void mma16816(float* d, const uint32_t* a, uint32_t b0, uint32_t b1) {
    asm volatile("mma.sync.aligned.m16n8k16.row.col.f32.f16.f16.f32 "
                 "{%0,%1,%2,%3}, {%4,%5,%6,%7}, {%8,%9}, {%0,%1,%2,%3};"
                 : "+f"(d[0]), "+f"(d[1]), "+f"(d[2]), "+f"(d[3])
                 : "r"(a[0]), "r"(a[1]), "r"(a[2]), "r"(a[3]), "r"(b0), "r"(b1));
}

// per-warp conv: features + L1 + fp16 convert for this warp's 16 rows.
template <int DIR>
__device__ __forceinline__ void conv_warp(char* sm, const float* __restrict__ x,
                                          const float* __restrict__ t, int b,
                                          int wid, int lane)
{
    const int r0 = wid * 16;
    float* sFeat = (float*)(sm + SM_FEAT);
    if (lane < 16) {
        const int m = r0 + lane, i = m;
        const float* xb = x + (size_t)b * 514;
        const float2 xi  = *(const float2*)(xb + i * 2);
        const float2 xi1 = *(const float2*)(xb + i * 2 + 2);
        const float2 pt  = *(const float2*)(xb + 512);
        const float tb = t[b];
        float* f = sFeat + m * 8;
        if (DIR == 0) { f[0]=xi1.x; f[1]=xi1.y; f[2]=tb; f[3]=xi.x;  f[4]=xi.y;  f[5]=(float)(i+1)*(1.f/256.f); }
        else          { f[0]=xi.x;  f[1]=xi.y;  f[2]=tb; f[3]=xi1.x; f[4]=xi1.y; f[5]=(float)i*(1.f/256.f); }
        f[6]=pt.x; f[7]=pt.y;
    }
    __syncwarp();

    const float* sW1 = (const float*)(sm + SM_W1);
    unsigned long long w1p[16];
    #pragma unroll
    for (int k = 0; k < 8; k++) {
        const ulonglong2 q = *(const ulonglong2*)(sW1 + k * 128 + lane * 4);
        w1p[2 * k] = q.x; w1p[2 * k + 1] = q.y;
    }
    const ulonglong2 b1q = *(const ulonglong2*)((const float*)(sm + SM_B1) + lane * 4);

    char* sa = sm + SM_A;
    const uint32_t chk = lane >> 1;
    const uint32_t halfsel = (lane & 1) * 8;
    #pragma unroll 4
    for (int j = 0; j < 16; j++) {
        const int m = r0 + j;
        const float* f = sFeat + m * 8;
        const float4 fa = *(const float4*)(f);
        const float4 fb = *(const float4*)(f + 4);
        unsigned long long a0 = b1q.x, a1 = b1q.y;
        a0 = ffma2(pack_dup(fa.x), w1p[0],  a0); a1 = ffma2(pack_dup(fa.x), w1p[1],  a1);
        a0 = ffma2(pack_dup(fa.y), w1p[2],  a0); a1 = ffma2(pack_dup(fa.y), w1p[3],  a1);
        a0 = ffma2(pack_dup(fa.z), w1p[4],  a0); a1 = ffma2(pack_dup(fa.z), w1p[5],  a1);
        a0 = ffma2(pack_dup(fa.w), w1p[6],  a0); a1 = ffma2(pack_dup(fa.w), w1p[7],  a1);
        a0 = ffma2(pack_dup(fb.x), w1p[8],  a0); a1 = ffma2(pack_dup(fb.x), w1p[9],  a1);
        a0 = ffma2(pack_dup(fb.y), w1p[10], a0); a1 = ffma2(pack_dup(fb.y), w1p[11], a1);
        a0 = ffma2(pack_dup(fb.z), w1p[12], a0); a1 = ffma2(pack_dup(fb.z), w1p[13], a1);
        a0 = ffma2(pack_dup(fb.w), w1p[14], a0); a1 = ffma2(pack_dup(fb.w), w1p[15], a1);
        const float2 v01 = unpack2(a0), v23 = unpack2(a1);
        const float v0 = fmaxf(v01.x, 0.f), v1 = fmaxf(v01.y, 0.f);
        const float v2 = fmaxf(v23.x, 0.f), v3 = fmaxf(v23.y, 0.f);
        const uint32_t h0 = cvt2hf(v1, v0), h1 = cvt2hf(v3, v2);
        const uint32_t off = (uint32_t)m * 256 + (((chk ^ (uint32_t)(m & 7)) << 4)) + halfsel;
        *(uint2*)(sa + off) = make_uint2(h0, h1);
    }
    __syncwarp();
}

template <int DIR>
__global__ void __launch_bounds__(NTHREADS, 1)
fused_kernel(const float* __restrict__ x, const float* __restrict__ t,
             const float* __restrict__ W1, const float* __restrict__ b1v,
             const float* __restrict__ W2, const float* __restrict__ b2v,
             const float* __restrict__ W3, const float* __restrict__ b3v,
             float* __restrict__ out, int ntiles)
{
    extern __shared__ __align__(1024) char sm[];
    const int tid = threadIdx.x, wid = tid >> 5, lane = tid & 31;
    const uint32_t smb = smem_u32_of(sm);

    // ---- prologue: transpose W2 into [n][k] fp16, small weights ----
    for (int idx = tid; idx < 16384; idx += NTHREADS) {
        const int n = idx >> 7, k = idx & 127;
        const float w = W2[k * 128 + n];
        const uint32_t off = (uint32_t)n * 256 + ((((uint32_t)(k >> 3) ^ (uint32_t)(n & 7)) << 4)) +
                             (uint32_t)(k & 7) * 2;
        *(__half*)(sm + SM_B + off) = __float2half_rn(w);
    }
    float* sW1 = (float*)(sm + SM_W1);
    for (int idx = tid; idx < 1024; idx += NTHREADS) sW1[idx] = W1[idx];
    if (tid < 128) {
        float4 e; e.x = b2v[tid]; e.y = W3[tid * 2]; e.z = W3[tid * 2 + 1]; e.w = 0.f;
        ((float4*)(sm + SM_EPI))[tid] = e;
        ((float*)(sm + SM_B1))[tid] = b1v[tid];
    }
    if (tid == 0) ((float2*)(sm + SM_B3))[0] = make_float2(b3v[0], b3v[1]);
    __syncthreads();

    const float2 b3 = ((const float2*)(sm + SM_B3))[0];

    // ldmatrix lane-address components
    const uint32_t rA = (uint32_t)(wid * 16) + (uint32_t)(lane & 15);
    const uint32_t rowA_off = rA * 256;
    const uint32_t rxA = rA & 7;
    const uint32_t cA_bit = (uint32_t)(lane >> 4);
    const uint32_t nB = (uint32_t)(lane & 7) + (uint32_t)((lane & 16) >> 1);
    const uint32_t rowB_off = nB * 256;
    const uint32_t rxB = nB & 7;
    const uint32_t cB_bit = (uint32_t)((lane >> 3) & 1);

    const uint32_t aA = smb + SM_A;
    const uint32_t bB = smb + SM_B;
    const float4* epi = (const float4*)(sm + SM_EPI);

    // Warp-staggered tile order (keeps warps de-phased).
    const int K = (ntiles + gridDim.x - 1) / (int)gridDim.x;
    const int off0 = (wid * K) >> 4;

    for (int k = 0; k < K; k++) {
        int kk = k + off0; if (kk >= K) kk -= K;
        const int tt = (int)blockIdx.x + kk * (int)gridDim.x;
        if (tt >= ntiles) continue;
        const int b = tt;                 // one 256-row tile per batch
        conv_warp<DIR>(sm, x, t, b, wid, lane);

        float acc[16][4];
        #pragma unroll
        for (int nb = 0; nb < 16; nb++)
            { acc[nb][0] = 0.f; acc[nb][1] = 0.f; acc[nb][2] = 0.f; acc[nb][3] = 0.f; }

        #pragma unroll 2
        for (int kb = 0; kb < 8; kb++) {
            const uint32_t cA = (uint32_t)(2 * kb) + cA_bit;
            const uint32_t offA = rowA_off + ((cA ^ rxA) << 4);
            uint32_t a[4];
            ldsm4(a, aA + offA);
            const uint32_t cB = (uint32_t)(2 * kb) + cB_bit;
            const uint32_t offB0 = rowB_off + ((cB ^ rxB) << 4);
            #pragma unroll
            for (int nb2 = 0; nb2 < 8; nb2++) {
                uint32_t bf[4];
                ldsm4(bf, bB + offB0 + (uint32_t)nb2 * 4096);
                mma16816(acc[2 * nb2],     a, bf[0], bf[1]);
                mma16816(acc[2 * nb2 + 1], a, bf[2], bf[3]);
            }
        }

        // ---- epilogue: relu(acc + b2) @ W3, 4-lane reduce, store ----
        float pa0 = 0.f, pa1 = 0.f, pb0 = 0.f, pb1 = 0.f;
        #pragma unroll
        for (int nb = 0; nb < 16; nb++) {
            const int col0 = nb * 8 + 2 * (lane & 3);
            const float4 e0 = epi[col0], e1 = epi[col0 + 1];
            float v;
            v = fmaxf(acc[nb][0] + e0.x, 0.f); pa0 += v * e0.y; pa1 += v * e0.z;
            v = fmaxf(acc[nb][1] + e1.x, 0.f); pa0 += v * e1.y; pa1 += v * e1.z;
            v = fmaxf(acc[nb][2] + e0.x, 0.f); pb0 += v * e0.y; pb1 += v * e0.z;
            v = fmaxf(acc[nb][3] + e1.x, 0.f); pb0 += v * e1.y; pb1 += v * e1.z;
        }
        #pragma unroll
        for (int s = 1; s <= 2; s <<= 1) {
            pa0 += __shfl_xor_sync(0xffffffffu, pa0, s);
            pa1 += __shfl_xor_sync(0xffffffffu, pa1, s);
            pb0 += __shfl_xor_sync(0xffffffffu, pb0, s);
            pb1 += __shfl_xor_sync(0xffffffffu, pb1, s);
        }
        if ((lane & 3) == 0) {
            const int q = lane >> 2;
            const int m1 = wid * 16 + q;      // rows m1 and m1+8
            const int i1 = m1, i2 = m1 + 8;
            float* ob = out + (size_t)b * 512;
            if (DIR == 0) {
                if (m1 == 0) *(float2*)ob = make_float2(0.f, 0.f);
                if (i1 < 255) *(float2*)(ob + (i1 + 1) * 2) = make_float2(pa0 + b3.x, pa1 + b3.y);
                if (i2 < 255) *(float2*)(ob + (i2 + 1) * 2) = make_float2(pb0 + b3.x, pb1 + b3.y);
            } else {
                if (i1 < 255) {
                    float2* o = (float2*)(ob + i1 * 2);
                    const float2 v = *o; *o = make_float2(v.x + pa0 + b3.x, v.y + pa1 + b3.y);
                }
                if (i2 < 255) {
                    float2* o = (float2*)(ob + i2 * 2);
                    const float2 v = *o; *o = make_float2(v.x + pb0 + b3.x, v.y + pb1 + b3.y);
                }
            }
        }
        __syncwarp();
    }
}

// ---------------- init MLP (3->128->128->2, 4096 rows) ----------------
__global__ void __launch_bounds__(128)
init_kernel(const float* __restrict__ x, const float* __restrict__ t,
            const float* __restrict__ W1, const float* __restrict__ b1,
            const float* __restrict__ W2, const float* __restrict__ b2,
            const float* __restrict__ W3, const float* __restrict__ b3,
            float* __restrict__ out, int nrows)
{
    extern __shared__ float ism[];
    float* sW2 = ism;           // 16384
    float* sh  = ism + 16384;   // 128
    float* red = ism + 16512;   // 8
    const int tid = threadIdx.x;
    for (int i = tid; i < 16384; i += 128) sW2[i] = W2[i];
    const float w10 = W1[tid], w11 = W1[128 + tid], w12 = W1[256 + tid];
    const float bb1 = b1[tid], bb2 = b2[tid];
    const float w30 = W3[tid * 2], w31 = W3[tid * 2 + 1];
    __syncthreads();
    for (int r = blockIdx.x; r < nrows; r += gridDim.x) {
        const float2 x0 = *(const float2*)(x + (size_t)r * 514);
        const float tb = t[r];
        sh[tid] = fmaxf(bb1 + x0.x * w10 + x0.y * w11 + tb * w12, 0.f);
        __syncthreads();
        float a = bb2;
        #pragma unroll 8
        for (int k = 0; k < 128; k++) a += sh[k] * sW2[k * 128 + tid];
        a = fmaxf(a, 0.f);
        float p0 = a * w30, p1 = a * w31;
        #pragma unroll
        for (int s = 16; s; s >>= 1) {
            p0 += __shfl_xor_sync(0xffffffffu, p0, s);
            p1 += __shfl_xor_sync(0xffffffffu, p1, s);
        }
        if ((tid & 31) == 0) { red[tid >> 5] = p0; red[4 + (tid >> 5)] = p1; }
        __syncthreads();
        if (tid == 0) {
            const float q0 = red[0] + red[1] + red[2] + red[3] + b3[0];
            const float q1 = red[4] + red[5] + red[6] + red[7] + b3[1];
            float2* o = (float2*)(out + (size_t)r * 512);
            const float2 v = *o; *o = make_float2(v.x + q0, v.y + q1);
        }
        __syncthreads();
    }
}

extern "C" void kernel_launch(void* const* d_in, const int* in_sizes, int n_in,
                              void* d_out, int out_size)
{
    (void)in_sizes; (void)n_in; (void)out_size;
    const float* x = (const float*)d_in[0];
    const float* t = (const float*)d_in[1];
    float* out = (float*)d_out;

    static int grid = 0;
    if (grid == 0) {
        int dev = 0, sms = 148;
        cudaGetDevice(&dev);
        cudaDeviceGetAttribute(&sms, cudaDevAttrMultiProcessorCount, dev);
        grid = sms;
        cudaFuncSetAttribute(fused_kernel<0>, cudaFuncAttributeMaxDynamicSharedMemorySize, SMEM_TOTAL);
        cudaFuncSetAttribute(fused_kernel<1>, cudaFuncAttributeMaxDynamicSharedMemorySize, SMEM_TOTAL);
        cudaFuncSetAttribute(init_kernel, cudaFuncAttributeMaxDynamicSharedMemorySize, 16520 * 4);
    }

    const int ntiles = N_B;       // one 256-row tile per batch

    fused_kernel<0><<<grid, NTHREADS, SMEM_TOTAL>>>(x, t,
        (const float*)d_in[2], (const float*)d_in[3], (const float*)d_in[4],
        (const float*)d_in[5], (const float*)d_in[6], (const float*)d_in[7], out, ntiles);
    fused_kernel<1><<<grid, NTHREADS, SMEM_TOTAL>>>(x, t,
        (const float*)d_in[8], (const float*)d_in[9], (const float*)d_in[10],
        (const float*)d_in[11], (const float*)d_in[12], (const float*)d_in[13], out, ntiles);
    init_kernel<<<304, 128, 16520 * 4>>>(x, t,
        (const float*)d_in[14], (const float*)d_in[15], (const float*)d_in[16],
        (const float*)d_in[17], (const float*)d_in[18], (const float*)d_in[19], out, N_B);
}

// round 11
// speedup vs baseline: 1.8132x; 1.0306x over previous
#include <cuda_runtime.h>
#include <cuda_fp16.h>
#include <cstdint>

#define N_B 4096
#define NTHREADS 256

// ---------------- smem layout (bytes) ----------------
#define SM_B     0        // 32768  W2 [n][k] fp16, swizzled
#define SM_A     32768    // 65536  A  [m=256][k] fp16, swizzled
#define SM_W1    98304    // 4096   W1 [k][col] f32
#define SM_EPI   102400   // 2048   per-col float4 {b2, w3_0, w3_1, 0}
#define SM_B1    104448   // 512
#define SM_FEAT  104960   // 8192   feat[256][8] f32
#define SM_B3    113152   // 8
#define SMEM_TOTAL 113216

// ---------------- helpers ----------------
__device__ __forceinline__ uint32_t smem_u32_of(const void* p) {
    uint32_t a;
    asm("{ .reg .u64 t; cvta.to.shared.u64 t, %1; cvt.u32.u64 %0, t; }" : "=r"(a) : "l"(p));
    return a;
}
__device__ __forceinline__ unsigned long long pack_dup(float v) {
    unsigned long long r; asm("mov.b64 %0, {%1, %1};" : "=l"(r) : "f"(v)); return r;
}
__device__ __forceinline__ unsigned long long ffma2(unsigned long long a, unsigned long long b,
                                                    unsigned long long c) {
    unsigned long long d; asm("fma.rn.f32x2 %0, %1, %2, %3;" : "=l"(d) : "l"(a), "l"(b), "l"(c));
    return d;
}
__device__ __forceinline__ float2 unpack2(unsigned long long v) {
    float2 r; asm("mov.b64 {%0, %1}, %2;" : "=f"(r.x), "=f"(r.y) : "l"(v)); return r;
}
__device__ __forceinline__ uint32_t cvt2hf(float hi, float lo) {  // hi->upper16, lo->lower16
    uint32_t r; asm("cvt.rn.f16x2.f32 %0, %1, %2;" : "=r"(r) : "f"(hi), "f"(lo)); return r;
}
__device__ __forceinline__ void ldsm4(uint32_t* r, uint32_t addr) {
    asm volatile("ldmatrix.sync.aligned.m8n8.x4.shared.b16 {%0,%1,%2,%3}, [%4];"
                 : "=r"(r[0]), "=r"(r[1]), "=r"(r[2]), "=r"(r[3]) : "r"(addr));
}
__device__ __forceinline__ void mma16816(float* d, const uint32_t* a, uint32_t b0, uint32_t b1) {
    asm volatile("mma.sync.aligned.m16n8k16.row.col.f32.f16.f16.f32 "
                 "{%0,%1,%2,%3}, {%4,%5,%6,%7}, {%8,%9}, {%0,%1,%2,%3};"
                 : "+f"(d[0]), "+f"(d[1]), "+f"(d[2]), "+f"(d[3])
                 : "r"(a[0]), "r"(a[1]), "r"(a[2]), "r"(a[3]), "r"(b0), "r"(b1));
}

// per-warp conv: features + L1 + fp16 convert for this warp's 32 rows.
template <int DIR>
__device__ __forceinline__ void conv_warp(char* sm, const float* __restrict__ x,
                                          const float* __restrict__ t, int b,
                                          int wid, int lane)
{
    const int r0 = wid * 32;
    float* sFeat = (float*)(sm + SM_FEAT);
    {
        const int m = r0 + lane, i = m;
        const float* xb = x + (size_t)b * 514;
        const float2 xi  = *(const float2*)(xb + i * 2);
        const float2 xi1 = *(const float2*)(xb + i * 2 + 2);
        const float2 pt  = *(const float2*)(xb + 512);
        const float tb = t[b];
        float* f = sFeat + m * 8;
        if (DIR == 0) { f[0]=xi1.x; f[1]=xi1.y; f[2]=tb; f[3]=xi.x;  f[4]=xi.y;  f[5]=(float)(i+1)*(1.f/256.f); }
        else          { f[0]=xi.x;  f[1]=xi.y;  f[2]=tb; f[3]=xi1.x; f[4]=xi1.y; f[5]=(float)i*(1.f/256.f); }
        f[6]=pt.x; f[7]=pt.y;
    }
    __syncwarp();

    const float* sW1 = (const float*)(sm + SM_W1);
    unsigned long long w1p[16];
    #pragma unroll
    for (int k = 0; k < 8; k++) {
        const ulonglong2 q = *(const ulonglong2*)(sW1 + k * 128 + lane * 4);
        w1p[2 * k] = q.x; w1p[2 * k + 1] = q.y;
    }
    const ulonglong2 b1q = *(const ulonglong2*)((const float*)(sm + SM_B1) + lane * 4);

    char* sa = sm + SM_A;
    const uint32_t chk = lane >> 1;
    const uint32_t halfsel = (lane & 1) * 8;
    #pragma unroll 4
    for (int j = 0; j < 32; j++) {
        const int m = r0 + j;
        const float* f = sFeat + m * 8;
        const float4 fa = *(const float4*)(f);
        const float4 fb = *(const float4*)(f + 4);
        unsigned long long a0 = b1q.x, a1 = b1q.y;
        a0 = ffma2(pack_dup(fa.x), w1p[0],  a0); a1 = ffma2(pack_dup(fa.x), w1p[1],  a1);
        a0 = ffma2(pack_dup(fa.y), w1p[2],  a0); a1 = ffma2(pack_dup(fa.y), w1p[3],  a1);
        a0 = ffma2(pack_dup(fa.z), w1p[4],  a0); a1 = ffma2(pack_dup(fa.z), w1p[5],  a1);
        a0 = ffma2(pack_dup(fa.w), w1p[6],  a0); a1 = ffma2(pack_dup(fa.w), w1p[7],  a1);
        a0 = ffma2(pack_dup(fb.x), w1p[8],  a0); a1 = ffma2(pack_dup(fb.x), w1p[9],  a1);
        a0 = ffma2(pack_dup(fb.y), w1p[10], a0); a1 = ffma2(pack_dup(fb.y), w1p[11], a1);
        a0 = ffma2(pack_dup(fb.z), w1p[12], a0); a1 = ffma2(pack_dup(fb.z), w1p[13], a1);
        a0 = ffma2(pack_dup(fb.w), w1p[14], a0); a1 = ffma2(pack_dup(fb.w), w1p[15], a1);
        const float2 v01 = unpack2(a0), v23 = unpack2(a1);
        const float v0 = fmaxf(v01.x, 0.f), v1 = fmaxf(v01.y, 0.f);
        const float v2 = fmaxf(v23.x, 0.f), v3 = fmaxf(v23.y, 0.f);
        const uint32_t h0 = cvt2hf(v1, v0), h1 = cvt2hf(v3, v2);
        const uint32_t off = (uint32_t)m * 256 + (((chk ^ (uint32_t)(m & 7)) << 4)) + halfsel;
        *(uint2*)(sa + off) = make_uint2(h0, h1);
    }
    __syncwarp();
}

template <int DIR>
__global__ void __launch_bounds__(NTHREADS, 1)
fused_kernel(const float* __restrict__ x, const float* __restrict__ t,
             const float* __restrict__ W1, const float* __restrict__ b1v,
             const float* __restrict__ W2, const float* __restrict__ b2v,
             const float* __restrict__ W3, const float* __restrict__ b3v,
             float* __restrict__ out, int ntiles)
{
    extern __shared__ __align__(1024) char sm[];
    const int tid = threadIdx.x, wid = tid >> 5, lane = tid & 31;
    const uint32_t smb = smem_u32_of(sm);

    // ---- prologue: transpose W2 into [n][k] fp16, small weights ----
    for (int idx = tid; idx < 16384; idx += NTHREADS) {
        const int n = idx >> 7, k = idx & 127;
        const float w = W2[k * 128 + n];
        const uint32_t off = (uint32_t)n * 256 + ((((uint32_t)(k >> 3) ^ (uint32_t)(n & 7)) << 4)) +
                             (uint32_t)(k & 7) * 2;
        *(__half*)(sm + SM_B + off) = __float2half_rn(w);
    }
    float* sW1 = (float*)(sm + SM_W1);
    for (int idx = tid; idx < 1024; idx += NTHREADS) sW1[idx] = W1[idx];
    if (tid < 128) {
        float4 e; e.x = b2v[tid]; e.y = W3[tid * 2]; e.z = W3[tid * 2 + 1]; e.w = 0.f;
        ((float4*)(sm + SM_EPI))[tid] = e;
        ((float*)(sm + SM_B1))[tid] = b1v[tid];
    }
    if (tid == 0) ((float2*)(sm + SM_B3))[0] = make_float2(b3v[0], b3v[1]);
    __syncthreads();

    const float2 b3 = ((const float2*)(sm + SM_B3))[0];

    // ldmatrix lane-address components (row group 0; group 1 is +16 rows = +4096B)
    const uint32_t rA = (uint32_t)(wid * 32) + (uint32_t)(lane & 15);
    const uint32_t rowA_off = rA * 256;
    const uint32_t rxA = rA & 7;
    const uint32_t cA_bit = (uint32_t)(lane >> 4);
    const uint32_t nB = (uint32_t)(lane & 7) + (uint32_t)((lane & 16) >> 1);
    const uint32_t rowB_off = nB * 256;
    const uint32_t rxB = nB & 7;
    const uint32_t cB_bit = (uint32_t)((lane >> 3) & 1);

    const uint32_t aA = smb + SM_A;
    const uint32_t bB = smb + SM_B;
    const float4* epi = (const float4*)(sm + SM_EPI);

    // Warp-staggered tile order (keeps warps de-phased).
    const int K = (ntiles + gridDim.x - 1) / (int)gridDim.x;
    const int off0 = (wid * K) >> 3;

    for (int k = 0; k < K; k++) {
        int kk = k + off0; if (kk >= K) kk -= K;
        const int tt = (int)blockIdx.x + kk * (int)gridDim.x;
        if (tt >= ntiles) continue;
        const int b = tt;                 // one 256-row tile per batch
        conv_warp<DIR>(sm, x, t, b, wid, lane);

        float acc[2][16][4];
        #pragma unroll
        for (int rg = 0; rg < 2; rg++)
            #pragma unroll
            for (int nb = 0; nb < 16; nb++)
                { acc[rg][nb][0]=0.f; acc[rg][nb][1]=0.f; acc[rg][nb][2]=0.f; acc[rg][nb][3]=0.f; }

        #pragma unroll 2
        for (int kb = 0; kb < 8; kb++) {
            const uint32_t cA = (uint32_t)(2 * kb) + cA_bit;
            const uint32_t offA0 = rowA_off + ((cA ^ rxA) << 4);
            uint32_t a0[4], a1[4];
            ldsm4(a0, aA + offA0);
            ldsm4(a1, aA + offA0 + 4096);
            const uint32_t cB = (uint32_t)(2 * kb) + cB_bit;
            const uint32_t offB0 = rowB_off + ((cB ^ rxB) << 4);
            #pragma unroll
            for (int nb2 = 0; nb2 < 8; nb2++) {
                uint32_t bf[4];
                ldsm4(bf, bB + offB0 + (uint32_t)nb2 * 4096);
                mma16816(acc[0][2 * nb2],     a0, bf[0], bf[1]);
                mma16816(acc[1][2 * nb2],     a1, bf[0], bf[1]);
                mma16816(acc[0][2 * nb2 + 1], a0, bf[2], bf[3]);
                mma16816(acc[1][2 * nb2 + 1], a1, bf[2], bf[3]);
            }
        }

        // ---- epilogue: relu(acc + b2) @ W3, 4-lane reduce, store ----
        float* ob = out + (size_t)b * 512;
        #pragma unroll
        for (int rg = 0; rg < 2; rg++) {
            float pa0 = 0.f, pa1 = 0.f, pb0 = 0.f, pb1 = 0.f;
            #pragma unroll
            for (int nb = 0; nb < 16; nb++) {
                const int col0 = nb * 8 + 2 * (lane & 3);
                const float4 e0 = epi[col0], e1 = epi[col0 + 1];
                float v;
                v = fmaxf(acc[rg][nb][0] + e0.x, 0.f); pa0 += v * e0.y; pa1 += v * e0.z;
                v = fmaxf(acc[rg][nb][1] + e1.x, 0.f); pa0 += v * e1.y; pa1 += v * e1.z;
                v = fmaxf(acc[rg][nb][2] + e0.x, 0.f); pb0 += v * e0.y; pb1 += v * e0.z;
                v = fmaxf(acc[rg][nb][3] + e1.x, 0.f); pb0 += v * e1.y; pb1 += v * e1.z;
            }
            #pragma unroll
            for (int s = 1; s <= 2; s <<= 1) {
                pa0 += __shfl_xor_sync(0xffffffffu, pa0, s);
                pa1 += __shfl_xor_sync(0xffffffffu, pa1, s);
                pb0 += __shfl_xor_sync(0xffffffffu, pb0, s);
                pb1 += __shfl_xor_sync(0xffffffffu, pb1, s);
            }
            if ((lane & 3) == 0) {
                const int q = lane >> 2;
                const int m1 = wid * 32 + rg * 16 + q;    // rows m1 and m1+8
                const int i1 = m1, i2 = m1 + 8;
                if (DIR == 0) {
                    if (m1 == 0) *(float2*)ob = make_float2(0.f, 0.f);
                    if (i1 < 255) *(float2*)(ob + (i1 + 1) * 2) = make_float2(pa0 + b3.x, pa1 + b3.y);
                    if (i2 < 255) *(float2*)(ob + (i2 + 1) * 2) = make_float2(pb0 + b3.x, pb1 + b3.y);
                } else {
                    if (i1 < 255) {
                        float2* o = (float2*)(ob + i1 * 2);
                        const float2 v = *o; *o = make_float2(v.x + pa0 + b3.x, v.y + pa1 + b3.y);
                    }
                    if (i2 < 255) {
                        float2* o = (float2*)(ob + i2 * 2);
                        const float2 v = *o; *o = make_float2(v.x + pb0 + b3.x, v.y + pb1 + b3.y);
                    }
                }
            }
        }
        __syncwarp();
    }
}

// ---------------- init MLP (3->128->128->2, 4096 rows) ----------------
__global__ void __launch_bounds__(128)
init_kernel(const float* __restrict__ x, const float* __restrict__ t,
            const float* __restrict__ W1, const float* __restrict__ b1,
            const float* __restrict__ W2, const float* __restrict__ b2,
            const float* __restrict__ W3, const float* __restrict__ b3,
            float* __restrict__ out, int nrows)
{
    extern __shared__ float ism[];
    float* sW2 = ism;           // 16384
    float* sh  = ism + 16384;   // 128
    float* red = ism + 16512;   // 8
    const int tid = threadIdx.x;
    for (int i = tid; i < 16384; i += 128) sW2[i] = W2[i];
    const float w10 = W1[tid], w11 = W1[128 + tid], w12 = W1[256 + tid];
    const float bb1 = b1[tid], bb2 = b2[tid];
    const float w30 = W3[tid * 2], w31 = W3[tid * 2 + 1];
    __syncthreads();
    for (int r = blockIdx.x; r < nrows; r += gridDim.x) {
        const float2 x0 = *(const float2*)(x + (size_t)r * 514);
        const float tb = t[r];
        sh[tid] = fmaxf(bb1 + x0.x * w10 + x0.y * w11 + tb * w12, 0.f);
        __syncthreads();
        float a = bb2;
        #pragma unroll 8
        for (int k = 0; k < 128; k++) a += sh[k] * sW2[k * 128 + tid];
        a = fmaxf(a, 0.f);
        float p0 = a * w30, p1 = a * w31;
        #pragma unroll
        for (int s = 16; s; s >>= 1) {
            p0 += __shfl_xor_sync(0xffffffffu, p0, s);
            p1 += __shfl_xor_sync(0xffffffffu, p1, s);
        }
        if ((tid & 31) == 0) { red[tid >> 5] = p0; red[4 + (tid >> 5)] = p1; }
        __syncthreads();
        if (tid == 0) {
            const float q0 = red[0] + red[1] + red[2] + red[3] + b3[0];
            const float q1 = red[4] + red[5] + red[6] + red[7] + b3[1];
            float2* o = (float2*)(out + (size_t)r * 512);
            const float2 v = *o; *o = make_float2(v.x + q0, v.y + q1);
        }
        __syncthreads();
    }
}

extern "C" void kernel_launch(void* const* d_in, const int* in_sizes, int n_in,
                              void* d_out, int out_size)
{
    (void)in_sizes; (void)n_in; (void)out_size;
    const float* x = (const float*)d_in[0];
    const float* t = (const float*)d_in[1];
    float* out = (float*)d_out;

    static int grid = 0;
    if (grid == 0) {
        int dev = 0, sms = 148;
        cudaGetDevice(&dev);
        cudaDeviceGetAttribute(&sms, cudaDevAttrMultiProcessorCount, dev);
        grid = sms;
        cudaFuncSetAttribute(fused_kernel<0>, cudaFuncAttributeMaxDynamicSharedMemorySize, SMEM_TOTAL);
        cudaFuncSetAttribute(fused_kernel<1>, cudaFuncAttributeMaxDynamicSharedMemorySize, SMEM_TOTAL);
        cudaFuncSetAttribute(init_kernel, cudaFuncAttributeMaxDynamicSharedMemorySize, 16520 * 4);
    }

    const int ntiles = N_B;       // one 256-row tile per batch

    fused_kernel<0><<<grid, NTHREADS, SMEM_TOTAL>>>(x, t,
        (const float*)d_in[2], (const float*)d_in[3], (const float*)d_in[4],
        (const float*)d_in[5], (const float*)d_in[6], (const float*)d_in[7], out, ntiles);
    fused_kernel<1><<<grid, NTHREADS, SMEM_TOTAL>>>(x, t,
        (const float*)d_in[8], (const float*)d_in[9], (const float*)d_in[10],
        (const float*)d_in[11], (const float*)d_in[12], (const float*)d_in[13], out, ntiles);
    init_kernel<<<304, 128, 16520 * 4>>>(x, t,
        (const float*)d_in[14], (const float*)d_in[15], (const float*)d_in[16],
        (const float*)d_in[17], (const float*)d_in[18], (const float*)d_in[19], out, N_B);
}